// round 1
// baseline (speedup 1.0000x reference)
#include <cuda_runtime.h>

#define NN 4096
#define BB 2
#define CC 64

typedef unsigned long long ull;

// Scratch (no allocations allowed): q,k as [B][8][N], v as [B][N][64]
__device__ float g_q[BB * 8 * NN];
__device__ float g_k[BB * 8 * NN];
__device__ float g_v[BB * NN * CC];

__device__ __forceinline__ ull pack2(float x) {
    ull r;
    asm("mov.b64 %0, {%1, %1};" : "=l"(r) : "r"(__float_as_uint(x)));
    return r;
}
// Packed f32x2 FMA (SASS FFMA2) — 2 FMAs per instruction, only reachable via PTX
#define FMA2(acc, a, b) asm("fma.rn.f32x2 %0, %1, %2, %0;" : "+l"(acc) : "l"(a), "l"(b))

// ---------------------------------------------------------------------------
// Kernel 1: q = Wq@x + bq, k = Wk@context + bk   -> g_q, g_k  [B][8][N]
// grid 512 x 256 threads; thread = one output element
// ---------------------------------------------------------------------------
__global__ void qk_kernel(const float* __restrict__ x, const float* __restrict__ ctx,
                          const float* __restrict__ Wq, const float* __restrict__ bq,
                          const float* __restrict__ Wk, const float* __restrict__ bk) {
    __shared__ float sW[16][64];
    __shared__ float sb[16];
    int tid = threadIdx.x;
    for (int i = tid; i < 512; i += 256) {
        sW[i >> 6][i & 63] = Wq[i];
        sW[8 + (i >> 6)][i & 63] = Wk[i];
    }
    if (tid < 8) { sb[tid] = bq[tid]; sb[8 + tid] = bk[tid]; }
    __syncthreads();

    int idx = blockIdx.x * 256 + tid;
    int n = idx & (NN - 1);
    int t = idx >> 12;            // 0..31
    int o = t & 15, b = t >> 4;
    const float* base = ((o < 8) ? x : ctx) + (size_t)b * CC * NN + n;
    float acc = sb[o];
#pragma unroll
    for (int c = 0; c < 64; c++) acc = fmaf(sW[o][c], base[(size_t)c * NN], acc);
    float* dst = (o < 8) ? g_q : g_k;
    dst[((b * 8) + (o & 7)) * NN + n] = acc;
}

// ---------------------------------------------------------------------------
// Kernel 2: v = Wv@context + bv  -> g_v [B][N][64] (transposed for attn reads)
// grid 2048 x 256 threads; thread = one output element (c fastest -> coalesced)
// ---------------------------------------------------------------------------
__global__ void v_kernel(const float* __restrict__ ctx, const float* __restrict__ Wv,
                         const float* __restrict__ bv) {
    __shared__ float sW[64][65];  // transposed [cc][c], padded
    __shared__ float sb[64];
    int tid = threadIdx.x;
    for (int i = tid; i < 4096; i += 256) sW[i & 63][i >> 6] = Wv[i];
    if (tid < 64) sb[tid] = bv[tid];
    __syncthreads();

    int idx = blockIdx.x * 256 + tid;
    int c = idx & 63;
    int m = (idx >> 6) & (NN - 1);
    int b = idx >> 18;
    const float* base = ctx + (size_t)b * CC * NN + m;
    float acc = sb[c];
#pragma unroll
    for (int cc = 0; cc < 64; cc++) acc = fmaf(sW[cc][c], base[(size_t)cc * NN], acc);
    g_v[idx] = acc;
}

// ---------------------------------------------------------------------------
// Kernel 3: single-pass flash attention (no running max needed: |energy| small)
//   grid (N/64, B), 256 threads. BQ=64 queries per CTA, MC=64 keys per chunk.
//   S-phase mapping: thread (qS = tid&63, mg = tid>>6) computes 16 s/p values.
//   O-phase mapping: thread (cg = tid&7, qg = tid>>3) owns 2 q-rows x 8 c-chans
//     (c-set {4cg..4cg+3} U {32+4cg..+3} so the two 128-bit sV loads per m are
//      bank-conflict-free).
// ---------------------------------------------------------------------------
__global__ __launch_bounds__(256, 1) void attn_kernel(const float* __restrict__ x,
                                                      const float* __restrict__ gammap,
                                                      float* __restrict__ out) {
    __shared__ float sQ[8][64];
    __shared__ float sK[8][64];
    __shared__ float sV[64][64];
    __shared__ float sP[64][66];   // [m][q], stride 66 => conflict-free both phases
    __shared__ float sRS[64][4];

    const int tid = threadIdx.x;
    const int b = blockIdx.y;
    const int q0 = blockIdx.x * 64;

    // S-phase mapping
    const int qS = tid & 63;
    const int mg = tid >> 6;
    const int m0 = mg * 16;
    // O-phase mapping
    const int cg = tid & 7;
    const int qg = tid >> 3;
    const int qa = 2 * qg;
    const int cLow = 4 * cg;
    const int cHigh = 32 + 4 * cg;

    // Load Q tile [8][64]
    for (int i = tid; i < 512; i += 256) {
        int c = i >> 6, qq = i & 63;
        sQ[c][qq] = g_q[((size_t)b * 8 + c) * NN + q0 + qq];
    }

    const float* gk = g_k + (size_t)b * 8 * NN;
    const float* gv = g_v + (size_t)b * NN * CC;

    // Register prefetch of chunk 0 (K: 2 floats/thread, V: 16 floats/thread)
    float2 kreg;
    float4 vreg[4];
    {
        int j = tid * 2;
        int kc = j >> 6, km = j & 63;
        kreg = *reinterpret_cast<const float2*>(&gk[(size_t)kc * NN + km]);
#pragma unroll
        for (int ii = 0; ii < 4; ii++) {
            int jj = (ii * 256 + tid) * 4;
            int vm = jj >> 6, vc = jj & 63;
            vreg[ii] = *reinterpret_cast<const float4*>(&gv[(size_t)vm * 64 + vc]);
        }
    }

    __syncthreads();
    // Broadcast q row into packed {q,q} registers (persistent)
    ull q2[8];
#pragma unroll
    for (int c = 0; c < 8; c++) q2[c] = pack2(sQ[c][qS]);

    ull accA[4] = {0, 0, 0, 0};  // q = qa
    ull accB[4] = {0, 0, 0, 0};  // q = qa+1
    float rs = 0.0f;             // partial rowsum for row qS over this thread's m-windows

    for (int ck = 0; ck < 64; ck++) {
        // Commit prefetched chunk to shared
        reinterpret_cast<float2*>(&sK[0][0])[tid] = kreg;
#pragma unroll
        for (int ii = 0; ii < 4; ii++)
            reinterpret_cast<float4*>(&sV[0][0])[ii * 256 + tid] = vreg[ii];

        // Prefetch next chunk into registers (hidden under S + O compute)
        if (ck < 63) {
            int k0n = (ck + 1) * 64;
            int j = tid * 2;
            int kc = j >> 6, km = j & 63;
            kreg = *reinterpret_cast<const float2*>(&gk[(size_t)kc * NN + k0n + km]);
#pragma unroll
            for (int ii = 0; ii < 4; ii++) {
                int jj = (ii * 256 + tid) * 4;
                int vm = jj >> 6, vc = jj & 63;
                vreg[ii] = *reinterpret_cast<const float4*>(&gv[((size_t)(k0n + vm)) * 64 + vc]);
            }
        }
        __syncthreads();

        // ---- S phase: s[qS][m0+0..15] = q . k, then p = exp(s) ----
        ull sacc[8];
#pragma unroll
        for (int p = 0; p < 8; p++) sacc[p] = 0ULL;
#pragma unroll
        for (int c = 0; c < 8; c++) {
#pragma unroll
            for (int p = 0; p < 8; p++) {
                ull kk = *reinterpret_cast<const ull*>(&sK[c][m0 + 2 * p]);
                FMA2(sacc[p], q2[c], kk);
            }
        }
#pragma unroll
        for (int p = 0; p < 8; p++) {
            float2 sv = *reinterpret_cast<float2*>(&sacc[p]);
            float e0 = __expf(sv.x);
            float e1 = __expf(sv.y);
            rs += e0 + e1;
            sP[m0 + 2 * p][qS] = e0;
            sP[m0 + 2 * p + 1][qS] = e1;
        }
        __syncthreads();

        // ---- O phase: O[q][c] += p[q][m] * V[m][c] ----
#pragma unroll 4
        for (int m = 0; m < 64; m++) {
            float2 pp = *reinterpret_cast<const float2*>(&sP[m][qa]);
            ull pa = pack2(pp.x);
            ull pb = pack2(pp.y);
            ulonglong2 vA = *reinterpret_cast<const ulonglong2*>(&sV[m][cLow]);
            ulonglong2 vB = *reinterpret_cast<const ulonglong2*>(&sV[m][cHigh]);
            FMA2(accA[0], pa, vA.x);
            FMA2(accA[1], pa, vA.y);
            FMA2(accA[2], pa, vB.x);
            FMA2(accA[3], pa, vB.y);
            FMA2(accB[0], pb, vA.x);
            FMA2(accB[1], pb, vA.y);
            FMA2(accB[2], pb, vB.x);
            FMA2(accB[3], pb, vB.y);
        }
        __syncthreads();
    }

    // Rowsum reduction (4 partials per row)
    sRS[qS][mg] = rs;
    __syncthreads();
    float rsA = sRS[qa][0] + sRS[qa][1] + sRS[qa][2] + sRS[qa][3];
    float rsB = sRS[qa + 1][0] + sRS[qa + 1][1] + sRS[qa + 1][2] + sRS[qa + 1][3];
    float gamma = gammap[0];
    float invA = gamma / rsA;
    float invB = gamma / rsB;

    // Epilogue: out = gamma * O / rowsum + x
    const size_t xbase = (size_t)b * CC * NN;
    int nA = q0 + qa, nB = nA + 1;
#pragma unroll
    for (int j = 0; j < 4; j++) {
        int c = (j < 2) ? (cLow + 2 * j) : (cHigh + 2 * (j - 2));
        float2 oa = *reinterpret_cast<float2*>(&accA[j]);
        float2 ob = *reinterpret_cast<float2*>(&accB[j]);
        size_t i0 = xbase + (size_t)c * NN;
        size_t i1 = xbase + (size_t)(c + 1) * NN;
        out[i0 + nA] = fmaf(oa.x, invA, x[i0 + nA]);
        out[i1 + nA] = fmaf(oa.y, invA, x[i1 + nA]);
        out[i0 + nB] = fmaf(ob.x, invB, x[i0 + nB]);
        out[i1 + nB] = fmaf(ob.y, invB, x[i1 + nB]);
    }
}

extern "C" void kernel_launch(void* const* d_in, const int* in_sizes, int n_in,
                              void* d_out, int out_size) {
    const float* x     = (const float*)d_in[0];
    const float* ctx   = (const float*)d_in[1];
    const float* Wq    = (const float*)d_in[2];
    const float* bq    = (const float*)d_in[3];
    const float* Wk    = (const float*)d_in[4];
    const float* bk    = (const float*)d_in[5];
    const float* Wv    = (const float*)d_in[6];
    const float* bv    = (const float*)d_in[7];
    const float* gamma = (const float*)d_in[8];
    float* out = (float*)d_out;

    qk_kernel<<<512, 256>>>(x, ctx, Wq, bq, Wk, bk);
    v_kernel<<<2048, 256>>>(ctx, Wv, bv);
    attn_kernel<<<dim3(NN / 64, BB), 256>>>(x, gamma, out);
}

// round 2
// speedup vs baseline: 1.0313x; 1.0313x over previous
#include <cuda_runtime.h>

#define NN 4096
#define BB 2
#define CC 64
#define MSPLIT 2

typedef unsigned long long ull;

// Scratch (no allocations allowed)
__device__ float g_q[BB * 8 * NN];                 // [B][8][N]
__device__ float g_k[BB * 8 * NN];                 // [B][8][N]
__device__ float g_v[BB * NN * CC];                // [B][N][64]
__device__ float g_po[MSPLIT * BB * NN * CC];      // partial O [s][b][n][c]
__device__ float g_prs[MSPLIT * BB * NN];          // partial rowsum [s][b][n]

__device__ __forceinline__ ull pack2(float x) {
    ull r;
    asm("mov.b64 %0, {%1, %1};" : "=l"(r) : "r"(__float_as_uint(x)));
    return r;
}
// Packed f32x2 FMA (SASS FFMA2) — 2 FMAs/instr, only reachable via PTX
#define FMA2(acc, a, b) asm("fma.rn.f32x2 %0, %1, %2, %0;" : "+l"(acc) : "l"(a), "l"(b))

// ---------------------------------------------------------------------------
// Kernel 1: q = Wq@x + bq, k = Wk@context + bk   -> g_q, g_k  [B][8][N]
// ---------------------------------------------------------------------------
__global__ void qk_kernel(const float* __restrict__ x, const float* __restrict__ ctx,
                          const float* __restrict__ Wq, const float* __restrict__ bq,
                          const float* __restrict__ Wk, const float* __restrict__ bk) {
    __shared__ float sW[16][64];
    __shared__ float sb[16];
    int tid = threadIdx.x;
    for (int i = tid; i < 512; i += 256) {
        sW[i >> 6][i & 63] = Wq[i];
        sW[8 + (i >> 6)][i & 63] = Wk[i];
    }
    if (tid < 8) { sb[tid] = bq[tid]; sb[8 + tid] = bk[tid]; }
    __syncthreads();

    int idx = blockIdx.x * 256 + tid;
    int n = idx & (NN - 1);
    int t = idx >> 12;            // 0..31
    int o = t & 15, b = t >> 4;
    const float* base = ((o < 8) ? x : ctx) + (size_t)b * CC * NN + n;
    float acc = sb[o];
#pragma unroll
    for (int c = 0; c < 64; c++) acc = fmaf(sW[o][c], base[(size_t)c * NN], acc);
    float* dst = (o < 8) ? g_q : g_k;
    dst[((b * 8) + (o & 7)) * NN + n] = acc;
}

// ---------------------------------------------------------------------------
// Kernel 2: v = Wv@context + bv  -> g_v [B][N][64]
// ---------------------------------------------------------------------------
__global__ void v_kernel(const float* __restrict__ ctx, const float* __restrict__ Wv,
                         const float* __restrict__ bv) {
    __shared__ float sW[64][65];
    __shared__ float sb[64];
    int tid = threadIdx.x;
    for (int i = tid; i < 4096; i += 256) sW[i & 63][i >> 6] = Wv[i];
    if (tid < 64) sb[tid] = bv[tid];
    __syncthreads();

    int idx = blockIdx.x * 256 + tid;
    int c = idx & 63;
    int m = (idx >> 6) & (NN - 1);
    int b = idx >> 18;
    const float* base = ctx + (size_t)b * CC * NN + m;
    float acc = sb[c];
#pragma unroll
    for (int cc = 0; cc < 64; cc++) acc = fmaf(sW[cc][c], base[(size_t)cc * NN], acc);
    g_v[idx] = acc;
}

// ---------------------------------------------------------------------------
// Kernel 3: flash attention, m-split partial pass (no running max needed).
//   grid (64 qtiles, B, MSPLIT), 256 threads, 2 CTAs/SM.
//   Double-buffered K/V chunks; 2 barriers/chunk; race-free.
//   Writes partial O [s][b][n][c] (unscaled) and partial rowsums.
// ---------------------------------------------------------------------------
__global__ __launch_bounds__(256, 2) void attn_kernel() {
    __shared__ __align__(16) float sK[2][8][64];
    __shared__ __align__(16) float sV[2][64][64];
    __shared__ __align__(16) float sP[64][66];   // [m][q]
    __shared__ float sRS[64][4];

    const int tid = threadIdx.x;
    const int b = blockIdx.y;
    const int q0 = blockIdx.x * 64;
    const int s = blockIdx.z;
    const int ck0 = s * 32;

    // S-phase mapping
    const int qS = tid & 63;
    const int mg = tid >> 6;
    const int m0 = mg * 16;
    // O-phase mapping
    const int cg = tid & 7;
    const int qg = tid >> 3;
    const int qa = 2 * qg;
    const int cLow = 4 * cg;
    const int cHigh = 32 + 4 * cg;

    const float* gk = g_k + (size_t)b * 8 * NN;
    const float* gv = g_v + (size_t)b * NN * CC;

    // Q row -> packed {q,q} registers
    ull q2[8];
#pragma unroll
    for (int c = 0; c < 8; c++) q2[c] = pack2(g_q[((size_t)b * 8 + c) * NN + q0 + qS]);

    // Prefetch + commit chunk ck0 into buffer 0
    const int kj = tid * 2, kc = kj >> 6, km = kj & 63;
    float2 kreg;
    float4 vreg[4];
    {
        int k0 = ck0 * 64;
        kreg = *reinterpret_cast<const float2*>(&gk[(size_t)kc * NN + k0 + km]);
#pragma unroll
        for (int ii = 0; ii < 4; ii++) {
            int jj = (ii * 256 + tid) * 4;
            int vm = jj >> 6, vc = jj & 63;
            vreg[ii] = *reinterpret_cast<const float4*>(&gv[(size_t)(k0 + vm) * CC + vc]);
        }
    }
    reinterpret_cast<float2*>(&sK[0][0][0])[tid] = kreg;
#pragma unroll
    for (int ii = 0; ii < 4; ii++)
        reinterpret_cast<float4*>(&sV[0][0][0])[ii * 256 + tid] = vreg[ii];
    __syncthreads();

    ull accA[4] = {0, 0, 0, 0};
    ull accB[4] = {0, 0, 0, 0};
    float rs = 0.0f;

    for (int li = 0; li < 32; li++) {
        const int buf = li & 1;

        // Prefetch next chunk into registers (hidden under S + O)
        if (li < 31) {
            int k0 = (ck0 + li + 1) * 64;
            kreg = *reinterpret_cast<const float2*>(&gk[(size_t)kc * NN + k0 + km]);
#pragma unroll
            for (int ii = 0; ii < 4; ii++) {
                int jj = (ii * 256 + tid) * 4;
                int vm = jj >> 6, vc = jj & 63;
                vreg[ii] = *reinterpret_cast<const float4*>(&gv[(size_t)(k0 + vm) * CC + vc]);
            }
        }

        // ---- S phase: s[qS][m0..m0+15] = q . k ; p = exp(s) ----
        ull sacc[8];
#pragma unroll
        for (int p = 0; p < 8; p++) sacc[p] = 0ULL;
#pragma unroll
        for (int c = 0; c < 8; c++) {
#pragma unroll
            for (int p = 0; p < 8; p++) {
                ull kk = *reinterpret_cast<const ull*>(&sK[buf][c][m0 + 2 * p]);
                FMA2(sacc[p], q2[c], kk);
            }
        }
#pragma unroll
        for (int p = 0; p < 8; p++) {
            float2 sv = *reinterpret_cast<float2*>(&sacc[p]);
            float e0 = __expf(sv.x);
            float e1 = __expf(sv.y);
            rs += e0 + e1;
            sP[m0 + 2 * p][qS] = e0;
            sP[m0 + 2 * p + 1][qS] = e1;
        }
        __syncthreads();

        // ---- O phase: O[q][c] += p[q][m] * V[m][c] ----
#pragma unroll 4
        for (int m = 0; m < 64; m++) {
            float2 pp = *reinterpret_cast<const float2*>(&sP[m][qa]);
            ull pa = pack2(pp.x);
            ull pb = pack2(pp.y);
            ulonglong2 vA = *reinterpret_cast<const ulonglong2*>(&sV[buf][m][cLow]);
            ulonglong2 vB = *reinterpret_cast<const ulonglong2*>(&sV[buf][m][cHigh]);
            FMA2(accA[0], pa, vA.x);
            FMA2(accA[1], pa, vA.y);
            FMA2(accA[2], pa, vB.x);
            FMA2(accA[3], pa, vB.y);
            FMA2(accB[0], pb, vA.x);
            FMA2(accB[1], pb, vA.y);
            FMA2(accB[2], pb, vB.x);
            FMA2(accB[3], pb, vB.y);
        }

        // Commit prefetched chunk to the other buffer (readers use `buf`)
        if (li < 31) {
            const int nb = buf ^ 1;
            reinterpret_cast<float2*>(&sK[nb][0][0])[tid] = kreg;
#pragma unroll
            for (int ii = 0; ii < 4; ii++)
                reinterpret_cast<float4*>(&sV[nb][0][0])[ii * 256 + tid] = vreg[ii];
        }
        __syncthreads();
    }

    // Rowsum partials -> global
    sRS[qS][mg] = rs;
    __syncthreads();
    if (tid < 64) {
        float r = sRS[tid][0] + sRS[tid][1] + sRS[tid][2] + sRS[tid][3];
        g_prs[((size_t)s * BB + b) * NN + q0 + tid] = r;
    }

    // Partial O -> global [s][b][n][c] (unscaled; combine kernel scales)
    const size_t base = (((size_t)s * BB + b) * NN + q0) * CC;
#pragma unroll
    for (int j = 0; j < 4; j++) {
        int c = (j < 2) ? (cLow + 2 * j) : (cHigh + 2 * (j - 2));
        *reinterpret_cast<float2*>(&g_po[base + (size_t)qa * CC + c]) =
            *reinterpret_cast<float2*>(&accA[j]);
        *reinterpret_cast<float2*>(&g_po[base + (size_t)(qa + 1) * CC + c]) =
            *reinterpret_cast<float2*>(&accB[j]);
    }
}

// ---------------------------------------------------------------------------
// Kernel 4: combine partials, scale, add residual, transpose to [b][c][n].
//   grid (64 n-tiles, B), 256 threads. All global I/O coalesced.
// ---------------------------------------------------------------------------
__global__ __launch_bounds__(256) void combine_kernel(const float* __restrict__ x,
                                                      const float* __restrict__ gammap,
                                                      float* __restrict__ out) {
    __shared__ float t[64][65];   // [c][n]
    __shared__ float inv[64];
    const int tid = threadIdx.x;
    const int b = blockIdx.y;
    const int n0 = blockIdx.x * 64;
    const float gamma = gammap[0];

    const size_t p0 = (((size_t)0 * BB + b) * NN + n0) * CC;
    const size_t p1 = (((size_t)1 * BB + b) * NN + n0) * CC;
    if (tid < 64) {
        float r = g_prs[((size_t)0 * BB + b) * NN + n0 + tid] +
                  g_prs[((size_t)1 * BB + b) * NN + n0 + tid];
        inv[tid] = gamma / r;
    }
#pragma unroll
    for (int k = 0; k < 16; k++) {
        int i = k * 256 + tid;
        int n = i >> 6, c = i & 63;
        t[c][n] = g_po[p0 + i] + g_po[p1 + i];
    }
    __syncthreads();

    const size_t xb = (size_t)b * CC * NN + n0;
#pragma unroll
    for (int k = 0; k < 16; k++) {
        int i = k * 256 + tid;
        int c = i >> 6, n = i & 63;
        size_t gi = xb + (size_t)c * NN + n;
        out[gi] = fmaf(t[c][n], inv[n], x[gi]);
    }
}

extern "C" void kernel_launch(void* const* d_in, const int* in_sizes, int n_in,
                              void* d_out, int out_size) {
    const float* x     = (const float*)d_in[0];
    const float* ctx   = (const float*)d_in[1];
    const float* Wq    = (const float*)d_in[2];
    const float* bq    = (const float*)d_in[3];
    const float* Wk    = (const float*)d_in[4];
    const float* bk    = (const float*)d_in[5];
    const float* Wv    = (const float*)d_in[6];
    const float* bv    = (const float*)d_in[7];
    const float* gamma = (const float*)d_in[8];
    float* out = (float*)d_out;

    qk_kernel<<<512, 256>>>(x, ctx, Wq, bq, Wk, bk);
    v_kernel<<<2048, 256>>>(ctx, Wv, bv);
    attn_kernel<<<dim3(64, BB, MSPLIT), 256>>>();
    combine_kernel<<<dim3(64, BB), 256>>>(x, gamma, out);
}

// round 3
// speedup vs baseline: 3.2039x; 3.1065x over previous
#include <cuda_runtime.h>
#include <cuda_bf16.h>

#define NN 4096
#define BB 2
#define CC 64

typedef unsigned int u32;

// Scratch (bf16, MMA-friendly layouts)
__device__ __nv_bfloat16 g_qh[(size_t)BB * NN * 8];   // [b][n][8c]
__device__ __nv_bfloat16 g_kh[(size_t)BB * NN * 8];   // [b][m][8c]
__device__ __nv_bfloat16 g_vh[(size_t)BB * CC * NN];  // [b][c][m]

__device__ __forceinline__ u32 packbf(float lo, float hi) {
    unsigned short a = __bfloat16_as_ushort(__float2bfloat16_rn(lo));
    unsigned short b = __bfloat16_as_ushort(__float2bfloat16_rn(hi));
    return (u32)a | ((u32)b << 16);
}

__device__ __forceinline__ void mma_bf16_k8(float d[4], u32 a0, u32 a1, u32 b0) {
    asm("mma.sync.aligned.m16n8k8.row.col.f32.bf16.bf16.f32 "
        "{%0,%1,%2,%3}, {%4,%5}, {%6}, {%0,%1,%2,%3};"
        : "+f"(d[0]), "+f"(d[1]), "+f"(d[2]), "+f"(d[3])
        : "r"(a0), "r"(a1), "r"(b0));
}
__device__ __forceinline__ void mma_bf16_k16(float d[4], u32 a0, u32 a1, u32 a2, u32 a3,
                                             u32 b0, u32 b1) {
    asm("mma.sync.aligned.m16n8k16.row.col.f32.bf16.bf16.f32 "
        "{%0,%1,%2,%3}, {%4,%5,%6,%7}, {%8,%9}, {%0,%1,%2,%3};"
        : "+f"(d[0]), "+f"(d[1]), "+f"(d[2]), "+f"(d[3])
        : "r"(a0), "r"(a1), "r"(a2), "r"(a3), "r"(b0), "r"(b1));
}

// ---------------------------------------------------------------------------
// Kernel 1: q = Wq@x + bq, k = Wk@context + bk -> bf16 [b][n][8]
// ---------------------------------------------------------------------------
__global__ void qk_kernel(const float* __restrict__ x, const float* __restrict__ ctx,
                          const float* __restrict__ Wq, const float* __restrict__ bq,
                          const float* __restrict__ Wk, const float* __restrict__ bk) {
    __shared__ float sW[16][64];
    __shared__ float sb[16];
    int tid = threadIdx.x;
    for (int i = tid; i < 512; i += 256) {
        sW[i >> 6][i & 63] = Wq[i];
        sW[8 + (i >> 6)][i & 63] = Wk[i];
    }
    if (tid < 8) { sb[tid] = bq[tid]; sb[8 + tid] = bk[tid]; }
    __syncthreads();

    int idx = blockIdx.x * 256 + tid;
    int n = idx & (NN - 1);
    int t = idx >> 12;            // 0..31
    int o = t & 15, b = t >> 4;
    const float* base = ((o < 8) ? x : ctx) + (size_t)b * CC * NN + n;
    float acc = sb[o];
#pragma unroll
    for (int c = 0; c < 64; c++) acc = fmaf(sW[o][c], base[(size_t)c * NN], acc);
    __nv_bfloat16* dst = (o < 8) ? g_qh : g_kh;
    dst[((size_t)b * NN + n) * 8 + (o & 7)] = __float2bfloat16_rn(acc);
}

// ---------------------------------------------------------------------------
// Kernel 2: v = Wv@context + bv -> bf16 [b][c][m], tiled over m
//   grid (64 m-tiles, B), 256 threads
// ---------------------------------------------------------------------------
__global__ __launch_bounds__(256) void v_kernel(const float* __restrict__ ctx,
                                                const float* __restrict__ Wv,
                                                const float* __restrict__ bv) {
    __shared__ float sW[64][65];   // [cc][c]
    __shared__ float sb[64];
    __shared__ float sC[64][68];   // [cc][m]
    int tid = threadIdx.x;
    int b = blockIdx.y;
    int m0 = blockIdx.x * 64;
    for (int i = tid; i < 4096; i += 256) sW[i & 63][i >> 6] = Wv[i];
    if (tid < 64) sb[tid] = bv[tid];
    {
        int cc = tid >> 2;
        const float4* src = (const float4*)(ctx + ((size_t)b * CC + cc) * NN + m0 + (tid & 3) * 16);
        float4* dst = (float4*)&sC[cc][(tid & 3) * 16];
        dst[0] = src[0]; dst[1] = src[1]; dst[2] = src[2]; dst[3] = src[3];
    }
    __syncthreads();

    int m = tid & 63;
    int cb = tid >> 6;
#pragma unroll
    for (int j = 0; j < 16; j++) {
        int c = cb * 16 + j;
        float acc = sb[c];
#pragma unroll
        for (int cc = 0; cc < 64; cc++) acc = fmaf(sW[cc][c], sC[cc][m], acc);
        g_vh[((size_t)b * CC + c) * NN + m0 + m] = __float2bfloat16_rn(acc);
    }
}

// ---------------------------------------------------------------------------
// Kernel 3: bf16 tensor-core flash attention (no max-subtract: |s| small).
//   grid (64 qtiles, B), 256 threads = 8 warps.
//   Warp w: query rows 16*(w&3)+..., m/c half h = w>>2.
//   S: 4x mma.m16n8k8 -> exp -> bf16 p -> sP.  O: 16x mma.m16n8k16.
//   Fused epilogue: rowsum, gamma/rs, smem transpose, +x residual.
// ---------------------------------------------------------------------------
__global__ __launch_bounds__(256, 1) void attn_kernel(const float* __restrict__ x,
                                                      const float* __restrict__ gammap,
                                                      float* __restrict__ out) {
    __shared__ __nv_bfloat16 sQ[64][8];        // [n][c]
    __shared__ __nv_bfloat16 sK[2][64][8];     // [m][c]
    __shared__ __nv_bfloat16 sV[2][64][72];    // [c][m] (pad 72)
    __shared__ __nv_bfloat16 sP[64][72];       // [n][m] (pad 72)
    __shared__ float sRS[64][2];
    __shared__ float sInv[64];
    __shared__ float sO[64][65];               // [n][c]

    const int tid = threadIdx.x;
    const int b = blockIdx.y;
    const int q0 = blockIdx.x * 64;
    const int w = tid >> 5;
    const int lane = tid & 31;
    const int g = lane >> 2;
    const int t = lane & 3;
    const int mT = w & 3;
    const int h = w >> 2;
    const float gamma = gammap[0];

    const char* gk = (const char*)g_kh + (size_t)b * NN * 8 * 2;
    const char* gv = (const char*)g_vh + (size_t)b * CC * NN * 2;

    // Q tile (1 KB, contiguous)
    ((u32*)sQ)[tid] = ((const u32*)((const char*)g_qh + ((size_t)b * NN + q0) * 16))[tid];

    // Prefetch + commit chunk 0
    u32 kreg;
    uint4 vreg0, vreg1;
    {
        kreg = *(const u32*)(gk + tid * 4);
        const char* vb = gv + ((size_t)(tid >> 2) * NN) * 2 + (tid & 3) * 32;
        vreg0 = *(const uint4*)(vb);
        vreg1 = *(const uint4*)(vb + 16);
    }
    ((u32*)sK[0])[tid] = kreg;
    {
        char* dst = (char*)sV[0] + (tid >> 2) * 144 + (tid & 3) * 32;
        *(uint4*)dst = vreg0;
        *(uint4*)(dst + 16) = vreg1;
    }
    __syncthreads();

    // Persistent Q fragment (rows 16*mT+g, 16*mT+8+g)
    const u32 qa0 = *(const u32*)((const char*)sQ + (16 * mT + g) * 16 + t * 4);
    const u32 qa1 = *(const u32*)((const char*)sQ + (16 * mT + 8 + g) * 16 + t * 4);

    float oC[4][4];
#pragma unroll
    for (int i = 0; i < 4; i++)
#pragma unroll
        for (int j = 0; j < 4; j++) oC[i][j] = 0.0f;
    float rsA = 0.0f, rsB = 0.0f;

    for (int ck = 0; ck < 64; ck++) {
        const int buf = ck & 1;

        // Prefetch next chunk into registers
        if (ck < 63) {
            int m0 = (ck + 1) * 64;
            kreg = *(const u32*)(gk + (size_t)m0 * 16 + tid * 4);
            const char* vb = gv + ((size_t)(tid >> 2) * NN + m0) * 2 + (tid & 3) * 32;
            vreg0 = *(const uint4*)(vb);
            vreg1 = *(const uint4*)(vb + 16);
        }

        // ---- S phase: E[16 rows][32h..32h+32] via 4x m16n8k8; exp; store p ----
        const int r = 16 * mT + g;
#pragma unroll
        for (int j = 0; j < 4; j++) {
            float e[4] = {0.0f, 0.0f, 0.0f, 0.0f};
            int mcol = 32 * h + 8 * j + g;
            u32 kb = *(const u32*)((const char*)sK[buf] + mcol * 16 + t * 4);
            mma_bf16_k8(e, qa0, qa1, kb);
            float p0 = __expf(e[0]), p1 = __expf(e[1]);
            float p2 = __expf(e[2]), p3 = __expf(e[3]);
            rsA += p0 + p1;
            rsB += p2 + p3;
            int mc = 32 * h + 8 * j + 2 * t;
            *(u32*)((char*)sP + r * 144 + mc * 2) = packbf(p0, p1);
            *(u32*)((char*)sP + (r + 8) * 144 + mc * 2) = packbf(p2, p3);
        }
        __syncthreads();

        // ---- O phase: O[16 rows][c in 32h..+32] += P * V, 4 k-steps ----
#pragma unroll
        for (int ks = 0; ks < 4; ks++) {
            int mA = 16 * ks + 2 * t;
            u32 a0 = *(const u32*)((const char*)sP + r * 144 + mA * 2);
            u32 a1 = *(const u32*)((const char*)sP + (r + 8) * 144 + mA * 2);
            u32 a2 = *(const u32*)((const char*)sP + r * 144 + (mA + 8) * 2);
            u32 a3 = *(const u32*)((const char*)sP + (r + 8) * 144 + (mA + 8) * 2);
#pragma unroll
            for (int cT = 0; cT < 4; cT++) {
                int c = 32 * h + 8 * cT + g;
                u32 b0 = *(const u32*)((const char*)sV[buf] + c * 144 + mA * 2);
                u32 b1 = *(const u32*)((const char*)sV[buf] + c * 144 + (mA + 8) * 2);
                mma_bf16_k16(oC[cT], a0, a1, a2, a3, b0, b1);
            }
        }

        // Commit prefetched chunk into the other buffer
        if (ck < 63) {
            ((u32*)sK[buf ^ 1])[tid] = kreg;
            char* dst = (char*)sV[buf ^ 1] + (tid >> 2) * 144 + (tid & 3) * 32;
            *(uint4*)dst = vreg0;
            *(uint4*)(dst + 16) = vreg1;
        }
        __syncthreads();
    }

    // Rowsum reduce (over lane quad), then across m-halves via smem
    rsA += __shfl_xor_sync(0xffffffffu, rsA, 1);
    rsA += __shfl_xor_sync(0xffffffffu, rsA, 2);
    rsB += __shfl_xor_sync(0xffffffffu, rsB, 1);
    rsB += __shfl_xor_sync(0xffffffffu, rsB, 2);
    if (t == 0) {
        sRS[16 * mT + g][h] = rsA;
        sRS[16 * mT + 8 + g][h] = rsB;
    }
    __syncthreads();
    if (tid < 64) sInv[tid] = gamma / (sRS[tid][0] + sRS[tid][1]);
    __syncthreads();

    // Scaled O -> sO[n][c]
    {
        int r = 16 * mT + g;
        float ivA = sInv[r], ivB = sInv[r + 8];
#pragma unroll
        for (int cT = 0; cT < 4; cT++) {
            int c = 32 * h + 8 * cT + 2 * t;
            sO[r][c] = oC[cT][0] * ivA;
            sO[r][c + 1] = oC[cT][1] * ivA;
            sO[r + 8][c] = oC[cT][2] * ivB;
            sO[r + 8][c + 1] = oC[cT][3] * ivB;
        }
    }
    __syncthreads();

    // Epilogue: out[b][c][q0+n] = sO[n][c] + x  (n fastest -> coalesced)
    {
        int n = tid & 63;
        int cb = tid >> 6;
#pragma unroll
        for (int j = 0; j < 16; j++) {
            int c = cb * 16 + j;
            size_t gi = ((size_t)b * CC + c) * NN + q0 + n;
            out[gi] = sO[n][c] + x[gi];
        }
    }
}

extern "C" void kernel_launch(void* const* d_in, const int* in_sizes, int n_in,
                              void* d_out, int out_size) {
    const float* x     = (const float*)d_in[0];
    const float* ctx   = (const float*)d_in[1];
    const float* Wq    = (const float*)d_in[2];
    const float* bq    = (const float*)d_in[3];
    const float* Wk    = (const float*)d_in[4];
    const float* bk    = (const float*)d_in[5];
    const float* Wv    = (const float*)d_in[6];
    const float* bv    = (const float*)d_in[7];
    const float* gamma = (const float*)d_in[8];
    float* out = (float*)d_out;

    qk_kernel<<<512, 256>>>(x, ctx, Wq, bq, Wk, bk);
    v_kernel<<<dim3(64, BB), 256>>>(ctx, Wv, bv);
    attn_kernel<<<dim3(64, BB), 256>>>(x, gamma, out);
}

// round 4
// speedup vs baseline: 3.7936x; 1.1841x over previous
#include <cuda_runtime.h>
#include <cuda_bf16.h>

#define NN 4096
#define BB 2
#define CC 64
#define MSPLIT 2

typedef unsigned int u32;

// Scratch
__device__ __nv_bfloat16 g_qh[(size_t)BB * NN * 8];        // [b][n][8c]
__device__ __nv_bfloat16 g_kh[(size_t)BB * NN * 8];        // [b][m][8c]
__device__ __nv_bfloat16 g_vh[(size_t)BB * CC * NN];       // [b][c][m]
__device__ float g_po[(size_t)MSPLIT * BB * CC * NN];      // partial O [s][b][c][n]
__device__ float g_prs[(size_t)MSPLIT * BB * NN];          // partial rowsum [s][b][n]

__device__ __forceinline__ u32 packbf(float lo, float hi) {
    unsigned short a = __bfloat16_as_ushort(__float2bfloat16_rn(lo));
    unsigned short b = __bfloat16_as_ushort(__float2bfloat16_rn(hi));
    return (u32)a | ((u32)b << 16);
}

__device__ __forceinline__ void mma_bf16_k8(float d[4], u32 a0, u32 a1, u32 b0) {
    asm("mma.sync.aligned.m16n8k8.row.col.f32.bf16.bf16.f32 "
        "{%0,%1,%2,%3}, {%4,%5}, {%6}, {%0,%1,%2,%3};"
        : "+f"(d[0]), "+f"(d[1]), "+f"(d[2]), "+f"(d[3])
        : "r"(a0), "r"(a1), "r"(b0));
}
__device__ __forceinline__ void mma_bf16_k16(float d[4], u32 a0, u32 a1, u32 a2, u32 a3,
                                             u32 b0, u32 b1) {
    asm("mma.sync.aligned.m16n8k16.row.col.f32.bf16.bf16.f32 "
        "{%0,%1,%2,%3}, {%4,%5,%6,%7}, {%8,%9}, {%0,%1,%2,%3};"
        : "+f"(d[0]), "+f"(d[1]), "+f"(d[2]), "+f"(d[3])
        : "r"(a0), "r"(a1), "r"(a2), "r"(a3), "r"(b0), "r"(b1));
}

// ---------------------------------------------------------------------------
// Kernel 1: q/k projections, tiled: each CTA reads its x/ctx tile ONCE.
//   grid (64 n-tiles, B), 256 threads.
// ---------------------------------------------------------------------------
__global__ __launch_bounds__(256) void qk_kernel(const float* __restrict__ x,
                                                 const float* __restrict__ ctx,
                                                 const float* __restrict__ Wq,
                                                 const float* __restrict__ bq,
                                                 const float* __restrict__ Wk,
                                                 const float* __restrict__ bk) {
    __shared__ float sx[64][68];
    __shared__ float sct[64][68];
    __shared__ float sW[16][64];
    __shared__ float sb[16];
    const int tid = threadIdx.x;
    const int b = blockIdx.y;
    const int n0 = blockIdx.x * 64;

    for (int i = tid; i < 512; i += 256) {
        sW[i >> 6][i & 63] = Wq[i];
        sW[8 + (i >> 6)][i & 63] = Wk[i];
    }
    if (tid < 8) { sb[tid] = bq[tid]; sb[8 + tid] = bk[tid]; }
#pragma unroll
    for (int k = 0; k < 8; k++) {
        int idx = k * 256 + tid;
        int r = idx >> 4, fc = (idx & 15) * 4;
        if (r < 64)
            *(float4*)&sx[r][fc] = *(const float4*)&x[((size_t)b * CC + r) * NN + n0 + fc];
        else
            *(float4*)&sct[r - 64][fc] = *(const float4*)&ctx[((size_t)b * CC + r - 64) * NN + n0 + fc];
    }
    __syncthreads();

    const int n = tid & 63;
    const int og = tid >> 6;           // 0,1: q rows 0-3/4-7; 2,3: k rows
    const int ob = (og & 1) * 4;
    const bool isk = og >= 2;
    const int wrow = (isk ? 8 : 0) + ob;
    float acc0 = sb[wrow], acc1 = sb[wrow + 1], acc2 = sb[wrow + 2], acc3 = sb[wrow + 3];
#pragma unroll
    for (int c = 0; c < 64; c++) {
        float v = isk ? sct[c][n] : sx[c][n];
        acc0 = fmaf(sW[wrow][c], v, acc0);
        acc1 = fmaf(sW[wrow + 1][c], v, acc1);
        acc2 = fmaf(sW[wrow + 2][c], v, acc2);
        acc3 = fmaf(sW[wrow + 3][c], v, acc3);
    }
    __nv_bfloat16* dst = isk ? g_kh : g_qh;
    u32* p = (u32*)(dst + ((size_t)b * NN + n0 + n) * 8 + ob);
    p[0] = packbf(acc0, acc1);
    p[1] = packbf(acc2, acc3);
}

// ---------------------------------------------------------------------------
// Kernel 2: v = Wv@ctx + bv -> bf16 [b][c][m]; register-blocked 4c x 4m.
//   grid (64 m-tiles, B), 256 threads.
// ---------------------------------------------------------------------------
__global__ __launch_bounds__(256) void v_kernel(const float* __restrict__ ctx,
                                                const float* __restrict__ Wv,
                                                const float* __restrict__ bv) {
    __shared__ float sW[64][68];   // [cc][c]
    __shared__ float sC[64][68];   // [cc][m]
    __shared__ float sb[64];
    const int tid = threadIdx.x;
    const int b = blockIdx.y;
    const int m0 = blockIdx.x * 64;

    for (int i = tid; i < 4096; i += 256) sW[i & 63][i >> 6] = Wv[i];
    if (tid < 64) sb[tid] = bv[tid];
#pragma unroll
    for (int k = 0; k < 4; k++) {
        int idx = k * 256 + tid;
        int r = idx >> 4, fc = (idx & 15) * 4;
        *(float4*)&sC[r][fc] = *(const float4*)&ctx[((size_t)b * CC + r) * NN + m0 + fc];
    }
    __syncthreads();

    const int mq = (tid & 15) * 4;
    const int cg = (tid >> 4) * 4;
    float acc[4][4];
#pragma unroll
    for (int i = 0; i < 4; i++)
#pragma unroll
        for (int j = 0; j < 4; j++) acc[i][j] = sb[cg + i];

#pragma unroll
    for (int cc = 0; cc < 64; cc++) {
        float4 vm = *(const float4*)&sC[cc][mq];
        float4 wv = *(const float4*)&sW[cc][cg];
        float vv[4] = {vm.x, vm.y, vm.z, vm.w};
        float ww[4] = {wv.x, wv.y, wv.z, wv.w};
#pragma unroll
        for (int i = 0; i < 4; i++)
#pragma unroll
            for (int j = 0; j < 4; j++) acc[i][j] = fmaf(ww[i], vv[j], acc[i][j]);
    }
#pragma unroll
    for (int i = 0; i < 4; i++) {
        u32 w0 = packbf(acc[i][0], acc[i][1]);
        u32 w1 = packbf(acc[i][2], acc[i][3]);
        u32* p = (u32*)(g_vh + ((size_t)b * CC + cg + i) * NN + m0 + mq);
        p[0] = w0;
        p[1] = w1;
    }
}

// ---------------------------------------------------------------------------
// Kernel 3: bf16 tensor-core flash attention, m-split partials.
//   grid (64 qtiles, B, MSPLIT), 256 threads = 8 warps, 2 CTAs/SM capable.
//   Named pair-barrier between S and O phases; full barrier per chunk.
//   Writes unscaled partial O [s][b][c][n] (coalesced) + partial rowsums.
// ---------------------------------------------------------------------------
__global__ __launch_bounds__(256, 2) void attn_kernel() {
    __shared__ __nv_bfloat16 sQ[64][8];
    __shared__ __nv_bfloat16 sK[2][64][8];
    __shared__ __nv_bfloat16 sV[2][64][72];
    __shared__ __align__(16) char uni[64 * 65 * 4];   // union: sP (bf16 64x72) / sO (f32 64x65)
    __shared__ float sRS[64][2];
    __nv_bfloat16 (*sP)[72] = (__nv_bfloat16 (*)[72])uni;
    float (*sO)[65] = (float (*)[65])uni;

    const int tid = threadIdx.x;
    const int b = blockIdx.y;
    const int q0 = blockIdx.x * 64;
    const int s = blockIdx.z;
    const int ck0 = s * 32;
    const int w = tid >> 5;
    const int lane = tid & 31;
    const int g = lane >> 2;
    const int t = lane & 3;
    const int mT = w & 3;
    const int h = w >> 2;

    const char* gk = (const char*)g_kh + (size_t)b * NN * 8 * 2;
    const char* gv = (const char*)g_vh + (size_t)b * CC * NN * 2;

    ((u32*)sQ)[tid] = ((const u32*)((const char*)g_qh + ((size_t)b * NN + q0) * 16))[tid];

    // Prefetch + commit chunk ck0 into buffer 0
    u32 kreg;
    uint4 vreg0, vreg1;
    {
        int m0 = ck0 * 64;
        kreg = *(const u32*)(gk + (size_t)m0 * 16 + tid * 4);
        const char* vb = gv + ((size_t)(tid >> 2) * NN + m0) * 2 + (tid & 3) * 32;
        vreg0 = *(const uint4*)(vb);
        vreg1 = *(const uint4*)(vb + 16);
    }
    ((u32*)sK[0])[tid] = kreg;
    {
        char* dst = (char*)sV[0] + (tid >> 2) * 144 + (tid & 3) * 32;
        *(uint4*)dst = vreg0;
        *(uint4*)(dst + 16) = vreg1;
    }
    __syncthreads();

    const u32 qa0 = *(const u32*)((const char*)sQ + (16 * mT + g) * 16 + t * 4);
    const u32 qa1 = *(const u32*)((const char*)sQ + (16 * mT + 8 + g) * 16 + t * 4);

    float oC[4][4];
#pragma unroll
    for (int i = 0; i < 4; i++)
#pragma unroll
        for (int j = 0; j < 4; j++) oC[i][j] = 0.0f;
    float rsA = 0.0f, rsB = 0.0f;
    const int r = 16 * mT + g;

    for (int ck = 0; ck < 32; ck++) {
        const int buf = ck & 1;

        if (ck < 31) {
            int m0 = (ck0 + ck + 1) * 64;
            kreg = *(const u32*)(gk + (size_t)m0 * 16 + tid * 4);
            const char* vb = gv + ((size_t)(tid >> 2) * NN + m0) * 2 + (tid & 3) * 32;
            vreg0 = *(const uint4*)(vb);
            vreg1 = *(const uint4*)(vb + 16);
        }

        // ---- S phase ----
#pragma unroll
        for (int j = 0; j < 4; j++) {
            float e[4] = {0.0f, 0.0f, 0.0f, 0.0f};
            int mcol = 32 * h + 8 * j + g;
            u32 kb = *(const u32*)((const char*)sK[buf] + mcol * 16 + t * 4);
            mma_bf16_k8(e, qa0, qa1, kb);
            float p0 = __expf(e[0]), p1 = __expf(e[1]);
            float p2 = __expf(e[2]), p3 = __expf(e[3]);
            rsA += p0 + p1;
            rsB += p2 + p3;
            int mc = 32 * h + 8 * j + 2 * t;
            *(u32*)((char*)sP + r * 144 + mc * 2) = packbf(p0, p1);
            *(u32*)((char*)sP + (r + 8) * 144 + mc * 2) = packbf(p2, p3);
        }
        // sP rows r,r+8 are produced/consumed by the (mT) warp pair only
        asm volatile("bar.sync %0, %1;" :: "r"(1 + mT), "r"(64) : "memory");

        // ---- O phase ----
#pragma unroll
        for (int ks = 0; ks < 4; ks++) {
            int mA = 16 * ks + 2 * t;
            u32 a0 = *(const u32*)((const char*)sP + r * 144 + mA * 2);
            u32 a1 = *(const u32*)((const char*)sP + (r + 8) * 144 + mA * 2);
            u32 a2 = *(const u32*)((const char*)sP + r * 144 + (mA + 8) * 2);
            u32 a3 = *(const u32*)((const char*)sP + (r + 8) * 144 + (mA + 8) * 2);
#pragma unroll
            for (int cT = 0; cT < 4; cT++) {
                int c = 32 * h + 8 * cT + g;
                u32 b0 = *(const u32*)((const char*)sV[buf] + c * 144 + mA * 2);
                u32 b1 = *(const u32*)((const char*)sV[buf] + c * 144 + (mA + 8) * 2);
                mma_bf16_k16(oC[cT], a0, a1, a2, a3, b0, b1);
            }
        }

        if (ck < 31) {
            ((u32*)sK[buf ^ 1])[tid] = kreg;
            char* dst = (char*)sV[buf ^ 1] + (tid >> 2) * 144 + (tid & 3) * 32;
            *(uint4*)dst = vreg0;
            *(uint4*)(dst + 16) = vreg1;
        }
        __syncthreads();
    }

    // Partial rowsums
    rsA += __shfl_xor_sync(0xffffffffu, rsA, 1);
    rsA += __shfl_xor_sync(0xffffffffu, rsA, 2);
    rsB += __shfl_xor_sync(0xffffffffu, rsB, 1);
    rsB += __shfl_xor_sync(0xffffffffu, rsB, 2);
    if (t == 0) {
        sRS[r][h] = rsA;
        sRS[r + 8][h] = rsB;
    }
    __syncthreads();   // also protects uni: sP -> sO transition
    if (tid < 64)
        g_prs[((size_t)s * BB + b) * NN + q0 + tid] = sRS[tid][0] + sRS[tid][1];

    // Raw O -> sO[n][c]
#pragma unroll
    for (int cT = 0; cT < 4; cT++) {
        int c = 32 * h + 8 * cT + 2 * t;
        sO[r][c] = oC[cT][0];
        sO[r][c + 1] = oC[cT][1];
        sO[r + 8][c] = oC[cT][2];
        sO[r + 8][c + 1] = oC[cT][3];
    }
    __syncthreads();

    // Coalesced partial-O store [s][b][c][q0+n]
    {
        int n = tid & 63;
        int cb = tid >> 6;
        float* po = g_po + ((size_t)s * BB + b) * CC * NN;
#pragma unroll
        for (int j = 0; j < 16; j++) {
            int c = cb * 16 + j;
            po[(size_t)c * NN + q0 + n] = sO[n][c];
        }
    }
}

// ---------------------------------------------------------------------------
// Kernel 4: streaming combine: out = gamma*(po0+po1)/rs + x. Fully coalesced.
//   grid 512 x 256 threads, float4 per thread.
// ---------------------------------------------------------------------------
__global__ __launch_bounds__(256) void combine_kernel(const float* __restrict__ x,
                                                      const float* __restrict__ gammap,
                                                      float* __restrict__ out) {
    const int idx = blockIdx.x * 256 + threadIdx.x;   // over BB*CC*NN/4
    const int n4 = idx & (NN / 4 - 1);
    const int c = (idx >> 10) & 63;
    const int b = idx >> 16;
    const float gamma = gammap[0];

    const size_t rsb0 = (size_t)(0 * BB + b) * NN + n4 * 4;
    const size_t rsb1 = (size_t)(1 * BB + b) * NN + n4 * 4;
    float4 r0 = *(const float4*)&g_prs[rsb0];
    float4 r1 = *(const float4*)&g_prs[rsb1];

    const size_t p0 = ((size_t)(0 * BB + b) * CC + c) * NN + n4 * 4;
    const size_t p1 = ((size_t)(1 * BB + b) * CC + c) * NN + n4 * 4;
    float4 o0 = *(const float4*)&g_po[p0];
    float4 o1 = *(const float4*)&g_po[p1];

    const size_t gi = ((size_t)b * CC + c) * NN + n4 * 4;
    float4 xv = *(const float4*)&x[gi];
    float4 res;
    res.x = fmaf((o0.x + o1.x), gamma / (r0.x + r1.x), xv.x);
    res.y = fmaf((o0.y + o1.y), gamma / (r0.y + r1.y), xv.y);
    res.z = fmaf((o0.z + o1.z), gamma / (r0.z + r1.z), xv.z);
    res.w = fmaf((o0.w + o1.w), gamma / (r0.w + r1.w), xv.w);
    *(float4*)&out[gi] = res;
}

extern "C" void kernel_launch(void* const* d_in, const int* in_sizes, int n_in,
                              void* d_out, int out_size) {
    const float* x     = (const float*)d_in[0];
    const float* ctx   = (const float*)d_in[1];
    const float* Wq    = (const float*)d_in[2];
    const float* bq    = (const float*)d_in[3];
    const float* Wk    = (const float*)d_in[4];
    const float* bk    = (const float*)d_in[5];
    const float* Wv    = (const float*)d_in[6];
    const float* bv    = (const float*)d_in[7];
    const float* gamma = (const float*)d_in[8];
    float* out = (float*)d_out;

    qk_kernel<<<dim3(64, BB), 256>>>(x, ctx, Wq, bq, Wk, bk);
    v_kernel<<<dim3(64, BB), 256>>>(ctx, Wv, bv);
    attn_kernel<<<dim3(64, BB, MSPLIT), 256>>>();
    combine_kernel<<<512, 256>>>(x, gamma, out);
}

// round 5
// speedup vs baseline: 4.6461x; 1.2247x over previous
#include <cuda_runtime.h>
#include <cuda_bf16.h>

#define NN 4096
#define BB 2
#define CC 64
#define MSPLIT 2

typedef unsigned int u32;

// Scratch
__device__ __nv_bfloat16 g_qh[(size_t)BB * NN * 8];        // [b][n][8c]
__device__ __nv_bfloat16 g_kh[(size_t)BB * NN * 8];        // [b][m][8c]
__device__ __nv_bfloat16 g_vh[(size_t)BB * CC * NN];       // [b][c][m]
__device__ __nv_bfloat16 g_po[(size_t)MSPLIT * BB * CC * NN]; // partial O [s][b][c][n] bf16
__device__ float g_prs[(size_t)MSPLIT * BB * NN];          // partial rowsum [s][b][n]
__device__ int g_tk[BB * 64];                              // tickets (parity-based, no reset)

__device__ __forceinline__ u32 packbf(float lo, float hi) {
    unsigned short a = __bfloat16_as_ushort(__float2bfloat16_rn(lo));
    unsigned short b = __bfloat16_as_ushort(__float2bfloat16_rn(hi));
    return (u32)a | ((u32)b << 16);
}
__device__ __forceinline__ float2 unpackbf(u32 v) {
    __nv_bfloat162 h = *(__nv_bfloat162*)&v;
    return make_float2(__bfloat162float(h.x), __bfloat162float(h.y));
}

__device__ __forceinline__ void mma_bf16_k8(float d[4], u32 a0, u32 a1, u32 b0) {
    asm("mma.sync.aligned.m16n8k8.row.col.f32.bf16.bf16.f32 "
        "{%0,%1,%2,%3}, {%4,%5}, {%6}, {%0,%1,%2,%3};"
        : "+f"(d[0]), "+f"(d[1]), "+f"(d[2]), "+f"(d[3])
        : "r"(a0), "r"(a1), "r"(b0));
}
__device__ __forceinline__ void mma_bf16_k16(float d[4], u32 a0, u32 a1, u32 a2, u32 a3,
                                             u32 b0, u32 b1) {
    asm("mma.sync.aligned.m16n8k16.row.col.f32.bf16.bf16.f32 "
        "{%0,%1,%2,%3}, {%4,%5,%6,%7}, {%8,%9}, {%0,%1,%2,%3};"
        : "+f"(d[0]), "+f"(d[1]), "+f"(d[2]), "+f"(d[3])
        : "r"(a0), "r"(a1), "r"(a2), "r"(a3), "r"(b0), "r"(b1));
}

// ---------------------------------------------------------------------------
// Kernel 1: q/k projections, tiled. grid (64, B), 256 threads.
// ---------------------------------------------------------------------------
__global__ __launch_bounds__(256) void qk_kernel(const float* __restrict__ x,
                                                 const float* __restrict__ ctx,
                                                 const float* __restrict__ Wq,
                                                 const float* __restrict__ bq,
                                                 const float* __restrict__ Wk,
                                                 const float* __restrict__ bk) {
    __shared__ float sx[64][68];
    __shared__ float sct[64][68];
    __shared__ float sW[16][64];
    __shared__ float sb[16];
    const int tid = threadIdx.x;
    const int b = blockIdx.y;
    const int n0 = blockIdx.x * 64;

    for (int i = tid; i < 512; i += 256) {
        sW[i >> 6][i & 63] = Wq[i];
        sW[8 + (i >> 6)][i & 63] = Wk[i];
    }
    if (tid < 8) { sb[tid] = bq[tid]; sb[8 + tid] = bk[tid]; }
#pragma unroll
    for (int k = 0; k < 8; k++) {
        int idx = k * 256 + tid;
        int r = idx >> 4, fc = (idx & 15) * 4;
        if (r < 64)
            *(float4*)&sx[r][fc] = *(const float4*)&x[((size_t)b * CC + r) * NN + n0 + fc];
        else
            *(float4*)&sct[r - 64][fc] = *(const float4*)&ctx[((size_t)b * CC + r - 64) * NN + n0 + fc];
    }
    __syncthreads();

    const int n = tid & 63;
    const int og = tid >> 6;
    const int ob = (og & 1) * 4;
    const bool isk = og >= 2;
    const int wrow = (isk ? 8 : 0) + ob;
    float acc0 = sb[wrow], acc1 = sb[wrow + 1], acc2 = sb[wrow + 2], acc3 = sb[wrow + 3];
#pragma unroll
    for (int c = 0; c < 64; c++) {
        float v = isk ? sct[c][n] : sx[c][n];
        acc0 = fmaf(sW[wrow][c], v, acc0);
        acc1 = fmaf(sW[wrow + 1][c], v, acc1);
        acc2 = fmaf(sW[wrow + 2][c], v, acc2);
        acc3 = fmaf(sW[wrow + 3][c], v, acc3);
    }
    __nv_bfloat16* dst = isk ? g_kh : g_qh;
    u32* p = (u32*)(dst + ((size_t)b * NN + n0 + n) * 8 + ob);
    p[0] = packbf(acc0, acc1);
    p[1] = packbf(acc2, acc3);
}

// ---------------------------------------------------------------------------
// Kernel 2: v projection, register-blocked 4c x 4m. grid (64, B), 256 threads.
// ---------------------------------------------------------------------------
__global__ __launch_bounds__(256) void v_kernel(const float* __restrict__ ctx,
                                                const float* __restrict__ Wv,
                                                const float* __restrict__ bv) {
    __shared__ float sW[64][68];
    __shared__ float sC[64][68];
    __shared__ float sb[64];
    const int tid = threadIdx.x;
    const int b = blockIdx.y;
    const int m0 = blockIdx.x * 64;

    for (int i = tid; i < 4096; i += 256) sW[i & 63][i >> 6] = Wv[i];
    if (tid < 64) sb[tid] = bv[tid];
#pragma unroll
    for (int k = 0; k < 4; k++) {
        int idx = k * 256 + tid;
        int r = idx >> 4, fc = (idx & 15) * 4;
        *(float4*)&sC[r][fc] = *(const float4*)&ctx[((size_t)b * CC + r) * NN + m0 + fc];
    }
    __syncthreads();

    const int mq = (tid & 15) * 4;
    const int cg = (tid >> 4) * 4;
    float acc[4][4];
#pragma unroll
    for (int i = 0; i < 4; i++)
#pragma unroll
        for (int j = 0; j < 4; j++) acc[i][j] = sb[cg + i];
#pragma unroll
    for (int cc = 0; cc < 64; cc++) {
        float4 vm = *(const float4*)&sC[cc][mq];
        float4 wv = *(const float4*)&sW[cc][cg];
        float vv[4] = {vm.x, vm.y, vm.z, vm.w};
        float ww[4] = {wv.x, wv.y, wv.z, wv.w};
#pragma unroll
        for (int i = 0; i < 4; i++)
#pragma unroll
            for (int j = 0; j < 4; j++) acc[i][j] = fmaf(ww[i], vv[j], acc[i][j]);
    }
#pragma unroll
    for (int i = 0; i < 4; i++) {
        u32 w0 = packbf(acc[i][0], acc[i][1]);
        u32 w1 = packbf(acc[i][2], acc[i][3]);
        u32* p = (u32*)(g_vh + ((size_t)b * CC + cg + i) * NN + m0 + mq);
        p[0] = w0;
        p[1] = w1;
    }
}

// ---------------------------------------------------------------------------
// Kernel 3: tensor-core flash attention, P-in-register, fused combine.
//   grid (64 qtiles, B, MSPLIT), 256 threads = 8 warps, 2 CTAs/SM.
//   Warp (qT = w&3, h = w>>2): 16 q-rows, m-half h. S-mma output frags ARE
//   the O-mma A frags after exp (no smem P). One barrier per chunk.
//   Cross-h O reduce in epilogue; partial bf16 O + rowsum to global; the
//   second-finishing CTA of each tile pair (ticket parity) runs the combine.
// ---------------------------------------------------------------------------
__global__ __launch_bounds__(256, 2) void attn_kernel(const float* __restrict__ x,
                                                      const float* __restrict__ gammap,
                                                      float* __restrict__ out) {
    __shared__ __nv_bfloat16 sQ[64][8];
    __shared__ __nv_bfloat16 sK[2][64][8];
    __shared__ __nv_bfloat16 sV[2][64][72];
    __shared__ float sO[64][65];
    __shared__ float sRS[64][2];
    __shared__ float sInv[64];
    __shared__ int sFlag;

    const int tid = threadIdx.x;
    const int b = blockIdx.y;
    const int q0 = blockIdx.x * 64;
    const int s = blockIdx.z;
    const int ck0 = s * 32;
    const int w = tid >> 5;
    const int lane = tid & 31;
    const int g = lane >> 2;
    const int t = lane & 3;
    const int qT = w & 3;
    const int h = w >> 2;
    const int r = 16 * qT + g;

    const char* gk = (const char*)g_kh + (size_t)b * NN * 8 * 2;
    const char* gv = (const char*)g_vh + (size_t)b * CC * NN * 2;

    ((u32*)sQ)[tid] = ((const u32*)((const char*)g_qh + ((size_t)b * NN + q0) * 16))[tid];

    // Prefetch + commit chunk ck0 into buffer 0
    u32 kreg;
    uint4 vreg0, vreg1;
    {
        int m0 = ck0 * 64;
        kreg = *(const u32*)(gk + (size_t)m0 * 16 + tid * 4);
        const char* vb = gv + ((size_t)(tid >> 2) * NN + m0) * 2 + (tid & 3) * 32;
        vreg0 = *(const uint4*)(vb);
        vreg1 = *(const uint4*)(vb + 16);
    }
    ((u32*)sK[0])[tid] = kreg;
    {
        char* dst = (char*)sV[0] + (tid >> 2) * 144 + (tid & 3) * 32;
        *(uint4*)dst = vreg0;
        *(uint4*)(dst + 16) = vreg1;
    }
    __syncthreads();

    const u32 qa0 = *(const u32*)((const char*)sQ + r * 16 + t * 4);
    const u32 qa1 = *(const u32*)((const char*)sQ + (r + 8) * 16 + t * 4);

    float oC[8][4];
#pragma unroll
    for (int i = 0; i < 8; i++)
#pragma unroll
        for (int j = 0; j < 4; j++) oC[i][j] = 0.0f;
    float rs0 = 0.0f, rs1 = 0.0f;

    for (int ck = 0; ck < 32; ck++) {
        const int buf = ck & 1;

        if (ck < 31) {
            int m0 = (ck0 + ck + 1) * 64;
            kreg = *(const u32*)(gk + (size_t)m0 * 16 + tid * 4);
            const char* vb = gv + ((size_t)(tid >> 2) * NN + m0) * 2 + (tid & 3) * 32;
            vreg0 = *(const uint4*)(vb);
            vreg1 = *(const uint4*)(vb + 16);
        }

        // ---- Fused S + exp + O, all in registers ----
#pragma unroll
        for (int ks = 0; ks < 2; ks++) {
            float e0[4] = {0.0f, 0.0f, 0.0f, 0.0f};
            float e1[4] = {0.0f, 0.0f, 0.0f, 0.0f};
            const int mc0 = 32 * h + 16 * ks + g;
            u32 kb0 = *(const u32*)((const char*)sK[buf] + mc0 * 16 + t * 4);
            u32 kb1 = *(const u32*)((const char*)sK[buf] + (mc0 + 8) * 16 + t * 4);
            mma_bf16_k8(e0, qa0, qa1, kb0);
            mma_bf16_k8(e1, qa0, qa1, kb1);

            float p00 = __expf(e0[0]), p01 = __expf(e0[1]);
            float p02 = __expf(e0[2]), p03 = __expf(e0[3]);
            float p10 = __expf(e1[0]), p11 = __expf(e1[1]);
            float p12 = __expf(e1[2]), p13 = __expf(e1[3]);
            rs0 += p00 + p01 + p10 + p11;
            rs1 += p02 + p03 + p12 + p13;
            u32 a0 = packbf(p00, p01);
            u32 a1 = packbf(p02, p03);
            u32 a2 = packbf(p10, p11);
            u32 a3 = packbf(p12, p13);

            const int mA = 32 * h + 16 * ks + 2 * t;
#pragma unroll
            for (int cT = 0; cT < 8; cT++) {
                int c = 8 * cT + g;
                u32 b0 = *(const u32*)((const char*)sV[buf] + c * 144 + mA * 2);
                u32 b1 = *(const u32*)((const char*)sV[buf] + c * 144 + (mA + 8) * 2);
                mma_bf16_k16(oC[cT], a0, a1, a2, a3, b0, b1);
            }
        }

        if (ck < 31) {
            ((u32*)sK[buf ^ 1])[tid] = kreg;
            char* dst = (char*)sV[buf ^ 1] + (tid >> 2) * 144 + (tid & 3) * 32;
            *(uint4*)dst = vreg0;
            *(uint4*)(dst + 16) = vreg1;
        }
        __syncthreads();
    }

    // Rowsum: reduce over t within quad, combine h halves via smem
    rs0 += __shfl_xor_sync(0xffffffffu, rs0, 1);
    rs0 += __shfl_xor_sync(0xffffffffu, rs0, 2);
    rs1 += __shfl_xor_sync(0xffffffffu, rs1, 1);
    rs1 += __shfl_xor_sync(0xffffffffu, rs1, 2);
    if (t == 0) {
        sRS[r][h] = rs0;
        sRS[r + 8][h] = rs1;
    }

    // Cross-h O reduce: h=0 writes, h=1 adds
    if (h == 0) {
#pragma unroll
        for (int cT = 0; cT < 8; cT++) {
            int c = 8 * cT + 2 * t;
            sO[r][c] = oC[cT][0];
            sO[r][c + 1] = oC[cT][1];
            sO[r + 8][c] = oC[cT][2];
            sO[r + 8][c + 1] = oC[cT][3];
        }
    }
    __syncthreads();
    if (h == 1) {
#pragma unroll
        for (int cT = 0; cT < 8; cT++) {
            int c = 8 * cT + 2 * t;
            sO[r][c] += oC[cT][0];
            sO[r][c + 1] += oC[cT][1];
            sO[r + 8][c] += oC[cT][2];
            sO[r + 8][c + 1] += oC[cT][3];
        }
    }
    __syncthreads();

    // Partial rowsum + partial bf16 O [s][b][c][n] (u32 = 2 n's)
    if (tid < 64)
        g_prs[((size_t)s * BB + b) * NN + q0 + tid] = sRS[tid][0] + sRS[tid][1];
    {
        u32* po = (u32*)g_po + ((size_t)s * BB + b) * (CC * NN / 2);
#pragma unroll
        for (int k = 0; k < 8; k++) {
            int idx = k * 256 + tid;
            int c = idx >> 5, n2 = idx & 31;
            po[(size_t)c * (NN / 2) + q0 / 2 + n2] = packbf(sO[2 * n2][c], sO[2 * n2 + 1][c]);
        }
    }

    // Ticket: second CTA of this (tile, b) pair performs the combine
    __threadfence();
    __syncthreads();
    if (tid == 0) sFlag = (atomicAdd(&g_tk[b * 64 + blockIdx.x], 1) & 1);
    __syncthreads();

    if (sFlag == 1) {
        __threadfence();
        if (tid < 64) {
            float ra = g_prs[(size_t)(0 * BB + b) * NN + q0 + tid];
            float rb = g_prs[(size_t)(1 * BB + b) * NN + q0 + tid];
            sInv[tid] = gammap[0] / (ra + rb);
        }
        __syncthreads();
        const u32* po0 = (const u32*)g_po + ((size_t)0 * BB + b) * (CC * NN / 2);
        const u32* po1 = (const u32*)g_po + ((size_t)1 * BB + b) * (CC * NN / 2);
#pragma unroll
        for (int k = 0; k < 8; k++) {
            int idx = k * 256 + tid;
            int c = idx >> 5, n2 = idx & 31;
            size_t pi = (size_t)c * (NN / 2) + q0 / 2 + n2;
            float2 v0 = unpackbf(po0[pi]);
            float2 v1 = unpackbf(po1[pi]);
            size_t gi = ((size_t)b * CC + c) * NN + q0 + 2 * n2;
            float2 xv = *(const float2*)&x[gi];
            float2 res;
            res.x = fmaf(v0.x + v1.x, sInv[2 * n2], xv.x);
            res.y = fmaf(v0.y + v1.y, sInv[2 * n2 + 1], xv.y);
            *(float2*)&out[gi] = res;
        }
    }
}

extern "C" void kernel_launch(void* const* d_in, const int* in_sizes, int n_in,
                              void* d_out, int out_size) {
    const float* x     = (const float*)d_in[0];
    const float* ctx   = (const float*)d_in[1];
    const float* Wq    = (const float*)d_in[2];
    const float* bq    = (const float*)d_in[3];
    const float* Wk    = (const float*)d_in[4];
    const float* bk    = (const float*)d_in[5];
    const float* Wv    = (const float*)d_in[6];
    const float* bv    = (const float*)d_in[7];
    const float* gamma = (const float*)d_in[8];
    float* out = (float*)d_out;

    qk_kernel<<<dim3(64, BB), 256>>>(x, ctx, Wq, bq, Wk, bk);
    v_kernel<<<dim3(64, BB), 256>>>(ctx, Wv, bv);
    attn_kernel<<<dim3(64, BB, MSPLIT), 256>>>(x, gamma, out);
}